// round 10
// baseline (speedup 1.0000x reference)
#include <cuda_runtime.h>

#define HW    16384
#define CCH   256
#define CHW   4194304   // 256*16384
#define NIMG  8

// per-(n,c) partial sums, two pixel-halves:
// g_accP[h*16384 + q*2048 + n*256 + c]
// q: 0 chS, 1 chT, 2 SS2, 3 SD, 4 FG, 5 BG, 6 CXS, 7 CXT
__device__ float  g_accP[2 * 16384];
__device__ float4 g_wpx[NIMG * HW];   // per-pixel: eT*mf, eT*bgi, ecS, ecT
__device__ float  g_eS[NIMG * HW];
__device__ float  g_eT[NIMG * HW];
__device__ float4 g_zpart[512];       // per passA block: zfeaS, zfeaT, zcmS, zcmT
__device__ float  g_bgpart[512];      // per passA block: bg pixel count
__device__ float  g_spart[NIMG];      // per-image spatial L1

__device__ __forceinline__ float warpSum(float v) {
#pragma unroll
    for (int o = 16; o; o >>= 1) v += __shfl_xor_sync(0xffffffffu, v, o);
    return v;
}

// ---------------- pass A: mask + per-pixel channel sums ----------------
// grid 512 = 8 images x 64 blocks of 256 pixels; thread t <-> pixel.
__global__ __launch_bounds__(256) void passA_kernel(
    const float* __restrict__ S, const float* __restrict__ T,
    const float* __restrict__ gt,
    const float* __restrict__ w_ms, const float* __restrict__ w_mt) {
    __shared__ float bx[100];
    __shared__ float wms[256], wmt[256];
    __shared__ float rb[5][8];
    int t = threadIdx.x, bid = blockIdx.x;
    int n = bid >> 6;
    int pix = (bid & 63) * 256 + t;
    if (t < 20) {
        const float* g4 = gt + (size_t)(n * 20 + t) * 4;
        float wmin = floorf(g4[0] * 0.125f);
        float hmin = floorf(g4[1] * 0.125f);
        float wmax = ceilf(g4[2] * 0.125f);
        float hmax = ceilf(g4[3] * 0.125f);
        bx[t]      = wmin;
        bx[20 + t] = wmax;
        bx[40 + t] = hmin;
        bx[60 + t] = hmax;
        bx[80 + t] = 1.f / ((hmax + 1.f - hmin) * (wmax + 1.f - wmin));
    }
    wms[t] = w_ms[t];
    wmt[t] = w_mt[t];
    __syncthreads();
    float h = (float)(pix >> 7), w = (float)(pix & 127);
    float mf = 0.f;
#pragma unroll
    for (int b = 0; b < 20; ++b) {
        bool in = (h >= bx[40 + b]) && (h <= bx[60 + b]) &&
                  (w >= bx[b]) && (w <= bx[20 + b]);
        mf = fmaxf(mf, in ? bx[80 + b] : 0.f);
    }
    float bgi = (mf > 0.f) ? 0.f : 1.f;

    const float* Sp = S + (size_t)n * CHW + pix;
    const float* Tp = T + (size_t)n * CHW + pix;
    float fS = 0, fT = 0, cS = 0, cT = 0;
#pragma unroll 8
    for (int c = 0; c < 256; ++c) {
        float sv = __ldg(Sp + (size_t)c * HW);
        float tv = __ldg(Tp + (size_t)c * HW);
        fS += fabsf(sv); fT += fabsf(tv);
        cS += sv * wms[c]; cT += tv * wmt[c];
    }
    float eS  = __expf(fS * (1.f / 128.f));   // fea/TEMP = sum/128
    float eT  = __expf(fT * (1.f / 128.f));
    float ecS = __expf(cS);                   // bias drops (softmax shift-inv)
    float ecT = __expf(cT);
    int gp = n * HW + pix;
    g_eS[gp] = eS;
    g_eT[gp] = eT;
    g_wpx[gp] = make_float4(eT * mf, eT * bgi, ecS, ecT);

    float v0 = warpSum(eS), v1 = warpSum(eT), v2 = warpSum(ecS);
    float v3 = warpSum(ecT), v4 = warpSum(bgi);
    int lane = t & 31, wid = t >> 5;
    if (lane == 0) {
        rb[0][wid] = v0; rb[1][wid] = v1; rb[2][wid] = v2;
        rb[3][wid] = v3; rb[4][wid] = v4;
    }
    __syncthreads();
    if (t == 0) {
        float z0 = 0, z1 = 0, z2 = 0, z3 = 0, zb = 0;
#pragma unroll
        for (int k = 0; k < 8; ++k) {
            z0 += rb[0][k]; z1 += rb[1][k]; z2 += rb[2][k];
            z3 += rb[3][k]; zb += rb[4][k];
        }
        g_zpart[bid] = make_float4(z0, z1, z2, z3);
        g_bgpart[bid] = zb;
    }
}

// ---------------- pass B: per-(n,c) weighted sums ----------------
// 256 blocks x 8 warps; warp <-> (image n, channel pair, pixel half).
// block b: n = b>>5, i5 = b&31: cgrp = i5>>1, half = i5&1.
// warp wid: cpair = cgrp*8 + wid, c0 = 2*cpair. 8192 px per warp, float4 lanes.
__device__ __forceinline__ void acc8(float* a, float sv, float tv, float4 wv) {
    float d = sv - tv, d2 = d * d;
    a[0] += fabsf(sv); a[1] += fabsf(tv);
    a[2] += d2;        a[3] += d;
    a[4] += d2 * wv.x; a[5] += d2 * wv.y;
    a[6] += sv * wv.z; a[7] += tv * wv.w;
}

__global__ __launch_bounds__(256) void passB_kernel(
    const float* __restrict__ S, const float* __restrict__ T) {
    int t = threadIdx.x, bid = blockIdx.x;
    int lane = t & 31, wid = t >> 5;
    int n = bid >> 5;
    int i5 = bid & 31;
    int half = i5 & 1;
    int c0 = ((i5 >> 1) * 8 + wid) * 2;
    size_t base = (size_t)n * CHW + (size_t)c0 * HW + half * 8192;
    const float4* S0 = reinterpret_cast<const float4*>(S + base);
    const float4* S1 = reinterpret_cast<const float4*>(S + base + HW);
    const float4* T0 = reinterpret_cast<const float4*>(T + base);
    const float4* T1 = reinterpret_cast<const float4*>(T + base + HW);
    const float4* W  = g_wpx + (size_t)n * HW + half * 8192;

    float a0[8], a1[8];
#pragma unroll
    for (int i = 0; i < 8; ++i) { a0[i] = 0.f; a1[i] = 0.f; }

#pragma unroll 2
    for (int it = 0; it < 64; ++it) {
        int q4 = it * 32 + lane;        // float4 index: px = q4*4
        float4 s0 = __ldg(S0 + q4);
        float4 t0 = __ldg(T0 + q4);
        float4 s1 = __ldg(S1 + q4);
        float4 t1 = __ldg(T1 + q4);
        float4 w0 = __ldg(W + q4 * 4 + 0);
        float4 w1 = __ldg(W + q4 * 4 + 1);
        float4 w2 = __ldg(W + q4 * 4 + 2);
        float4 w3 = __ldg(W + q4 * 4 + 3);
        acc8(a0, s0.x, t0.x, w0); acc8(a0, s0.y, t0.y, w1);
        acc8(a0, s0.z, t0.z, w2); acc8(a0, s0.w, t0.w, w3);
        acc8(a1, s1.x, t1.x, w0); acc8(a1, s1.y, t1.y, w1);
        acc8(a1, s1.z, t1.z, w2); acc8(a1, s1.w, t1.w, w3);
    }
#pragma unroll
    for (int i = 0; i < 8; ++i) { a0[i] = warpSum(a0[i]); a1[i] = warpSum(a1[i]); }
    if (lane == 0) {
        float* dst = g_accP + half * 16384 + n * 256;
#pragma unroll
        for (int q = 0; q < 8; ++q) {
            dst[q * 2048 + c0]     = a0[q];
            dst[q * 2048 + c0 + 1] = a1[q];
        }
    }
}

// ---------------- spatial attention L1: one block per image ----------------
__global__ __launch_bounds__(256) void spat_kernel() {
    int n = blockIdx.x, t = threadIdx.x;
    int lane = t & 31, wid = t >> 5;
    __shared__ float zz[2];
    __shared__ float r2[8];
    if (t < 32) {
        float4 za = g_zpart[n * 64 + t];
        float4 zb = g_zpart[n * 64 + 32 + t];
        float zs = warpSum(za.x + zb.x);
        float zt = warpSum(za.y + zb.y);
        if (t == 0) { zz[0] = zs; zz[1] = zt; }
    }
    __syncthreads();
    float is = 16384.f / zz[0], it = 16384.f / zz[1];
    const float* eSp = g_eS + (size_t)n * HW;
    const float* eTp = g_eT + (size_t)n * HW;
    float v = 0.f;
#pragma unroll 4
    for (int chunk = 0; chunk < 64; ++chunk) {
        int px = chunk * 256 + t;
        v += fabsf(eSp[px] * is - eTp[px] * it);
    }
    v = warpSum(v);
    if (lane == 0) r2[wid] = v;
    __syncthreads();
    if (t == 0) {
        float s2 = 0;
#pragma unroll
        for (int k = 0; k < 8; ++k) s2 += r2[k];
        g_spart[n] = s2;
    }
}

// ---------------- epilogue: channel softmax, MLPs, combine ----------------
#define ACC(q, i) (g_accP[(q) * 2048 + (i)] + g_accP[16384 + (q) * 2048 + (i)])

__device__ void channel_mlp(const float* __restrict__ ctx,
                            const float* __restrict__ w1, const float* __restrict__ b1,
                            const float* __restrict__ gam, const float* __restrict__ bet,
                            const float* __restrict__ w2, const float* __restrict__ b2,
                            float* __restrict__ yS, float* __restrict__ outp) {
    int t = threadIdx.x, w = t >> 5, lane = t & 31;
    const float4* ctx4 = reinterpret_cast<const float4*>(ctx + w * 256);
    float acc[4];
#pragma unroll
    for (int k = 0; k < 4; ++k) acc[k] = b1[lane + 32 * k];
    for (int c4 = 0; c4 < 64; ++c4) {
        float4 cv = ctx4[c4];
#pragma unroll
        for (int k = 0; k < 4; ++k) {
            float4 wv = *reinterpret_cast<const float4*>(w1 + (size_t)(lane + 32 * k) * 256 + c4 * 4);
            acc[k] += cv.x * wv.x + cv.y * wv.y + cv.z * wv.z + cv.w * wv.w;
        }
    }
    float s = 0, s2 = 0;
#pragma unroll
    for (int k = 0; k < 4; ++k) { s += acc[k]; s2 += acc[k] * acc[k]; }
    s = warpSum(s); s2 = warpSum(s2);
    float mean = s * (1.f / 128.f);
    float var = s2 * (1.f / 128.f) - mean * mean;
    float inv = rsqrtf(var + 1e-5f);
#pragma unroll
    for (int k = 0; k < 4; ++k) {
        int j = lane + 32 * k;
        float y = (acc[k] - mean) * inv * gam[j] + bet[j];
        yS[w * 128 + j] = fmaxf(y, 0.f);
    }
    __syncwarp();
    const float4* y4 = reinterpret_cast<const float4*>(yS + w * 128);
    float o[8];
#pragma unroll
    for (int k = 0; k < 8; ++k) o[k] = b2[lane + 32 * k];
    for (int j4 = 0; j4 < 32; ++j4) {
        float4 yv = y4[j4];
#pragma unroll
        for (int k = 0; k < 8; ++k) {
            float4 wv = *reinterpret_cast<const float4*>(w2 + (size_t)(lane + 32 * k) * 128 + j4 * 4);
            o[k] += yv.x * wv.x + yv.y * wv.y + yv.z * wv.z + yv.w * wv.w;
        }
    }
    __syncwarp();
#pragma unroll
    for (int k = 0; k < 8; ++k) outp[w * 256 + lane + 32 * k] = o[k];
    __syncthreads();
}

__global__ __launch_bounds__(256) void final_kernel(
    const float* __restrict__ w1_s, const float* __restrict__ b1_s,
    const float* __restrict__ g_s,  const float* __restrict__ be_s,
    const float* __restrict__ w2_s, const float* __restrict__ b2_s,
    const float* __restrict__ w1_t, const float* __restrict__ b1_t,
    const float* __restrict__ g_t,  const float* __restrict__ be_t,
    const float* __restrict__ w2_t, const float* __restrict__ b2_t,
    float* __restrict__ out) {
    __shared__ __align__(16) float shFS[2048];
    __shared__ __align__(16) float shFT[2048];
    __shared__ __align__(16) float shCS[2048];
    __shared__ __align__(16) float shCT[2048];
    __shared__ __align__(16) float shY[1024];
    __shared__ float shZT[8], shZcS[8], shZcT[8], shBG[8];
    __shared__ float shZ[16];
    __shared__ float shR[8];
    int t = threadIdx.x, w = t >> 5, lane = t & 31;
    {
        float4 za = g_zpart[w * 64 + lane];
        float4 zb = g_zpart[w * 64 + 32 + lane];
        float zt  = warpSum(za.y + zb.y);
        float zcs = warpSum(za.z + zb.z);
        float zct = warpSum(za.w + zb.w);
        float bg  = warpSum(g_bgpart[w * 64 + lane] + g_bgpart[w * 64 + 32 + lane]);
        if (lane == 0) { shZT[w] = zt; shZcS[w] = zcs; shZcT[w] = zct; shBG[w] = bg; }
    }
    __syncthreads();
#pragma unroll
    for (int n = 0; n < 8; ++n) {
        int i = n * 256 + t;
        shFS[i] = __expf(ACC(0, i) * (1.f / 8192.f));   // ch/TEMP = sum/8192
        shFT[i] = __expf(ACC(1, i) * (1.f / 8192.f));
        shCS[i] = ACC(6, i) / shZcS[n];
        shCT[i] = ACC(7, i) / shZcT[n];
    }
    __syncthreads();
    {
        float zS = 0, zT = 0;
#pragma unroll
        for (int k = 0; k < 8; ++k) {
            int c = lane + 32 * k;
            zS += shFS[w * 256 + c];
            zT += shFT[w * 256 + c];
        }
        zS = warpSum(zS); zT = warpSum(zT);
        if (lane == 0) { shZ[w] = zS; shZ[8 + w] = zT; }
    }
    __syncthreads();
    channel_mlp(shCS, w1_s, b1_s, g_s, be_s, w2_s, b2_s, shY, shCS);  // -> add_s
    channel_mlp(shCT, w1_t, b1_t, g_t, be_t, w2_t, b2_t, shY, shCT);  // -> add_t

    float acc = 0.f;
#pragma unroll
    for (int n = 0; n < 8; ++n) {
        int i = n * 256 + t;
        float cS = 256.f * shFS[i] / shZ[n];
        float cT = 256.f * shFT[i] / shZ[8 + n];
        float wn = cT * (16384.f / shZT[n]);
        float bgc = shBG[n];
        float bgw = (bgc > 0.f) ? (1.f / bgc) : 0.f;
        float fg = wn * ACC(4, i);
        float bg = wn * bgw * ACC(5, i);
        float mC = fabsf(cS - cT);
        float delta = shCS[i] - shCT[i];
        float rel = ACC(2, i) + 2.f * delta * ACC(3, i)
                    + 16384.f * delta * delta;
        acc += 1e-3f * fg + 5e-4f * bg + 1e-3f * mC + 5e-6f * rel;
    }
    acc = warpSum(acc);
    if (lane == 0) shR[w] = acc;
    __syncthreads();
    if (t < 32) {
        float x = (t < 8) ? shR[t] : 0.f;
        x = warpSum(x);
        if (t == 0) {
            float sp = 0;
#pragma unroll
            for (int k = 0; k < 8; ++k) sp += g_spart[k];
            out[0] = (x + 1e-3f * sp) * 0.125f;
        }
    }
}

extern "C" void kernel_launch(void* const* d_in, const int* in_sizes, int n_in,
                              void* d_out, int out_size) {
    const float* S    = (const float*)d_in[0];
    const float* T    = (const float*)d_in[1];
    const float* gt   = (const float*)d_in[2];
    const float* w_ms = (const float*)d_in[3];
    const float* w_mt = (const float*)d_in[5];
    const float* w1_s = (const float*)d_in[7];
    const float* b1_s = (const float*)d_in[8];
    const float* g_s  = (const float*)d_in[9];
    const float* be_s = (const float*)d_in[10];
    const float* w2_s = (const float*)d_in[11];
    const float* b2_s = (const float*)d_in[12];
    const float* w1_t = (const float*)d_in[13];
    const float* b1_t = (const float*)d_in[14];
    const float* g_t  = (const float*)d_in[15];
    const float* be_t = (const float*)d_in[16];
    const float* w2_t = (const float*)d_in[17];
    const float* b2_t = (const float*)d_in[18];

    passA_kernel<<<512, 256>>>(S, T, gt, w_ms, w_mt);
    passB_kernel<<<256, 256>>>(S, T);
    spat_kernel<<<8, 256>>>();
    final_kernel<<<1, 256>>>(w1_s, b1_s, g_s, be_s, w2_s, b2_s,
                             w1_t, b1_t, g_t, be_t, w2_t, b2_t,
                             (float*)d_out);
}

// round 12
// speedup vs baseline: 1.5767x; 1.5767x over previous
#include <cuda_runtime.h>

#define HW    16384
#define CCH   256
#define CHW   4194304   // 256*16384
#define NIMG  8

// per-(n,c) partial sums, two pixel-halves:
// g_accP[h*16384 + q*2048 + n*256 + c]
// q: 0 chS, 1 chT, 2 SS2, 3 SD, 4 FG, 5 BG, 6 CXS, 7 CXT
__device__ float  g_accP[2 * 16384];
__device__ float4 g_wpx[NIMG * HW];   // per-pixel: eT*mf, eT*bgi, ecS, ecT
__device__ float  g_eS[NIMG * HW];
__device__ float  g_eT[NIMG * HW];
__device__ float4 g_zpart[512];       // per passA block: zfeaS, zfeaT, zcmS, zcmT
__device__ float  g_bgpart[512];      // per passA block: bg pixel count
__device__ float  g_spart[NIMG];      // per-image spatial L1

__device__ __forceinline__ float warpSum(float v) {
#pragma unroll
    for (int o = 16; o; o >>= 1) v += __shfl_xor_sync(0xffffffffu, v, o);
    return v;
}

// ---------------- pass A: mask + per-pixel channel sums ----------------
// grid 512 = 8 images x 64 blocks of 256 pixels; thread t <-> pixel.
__global__ __launch_bounds__(256) void passA_kernel(
    const float* __restrict__ S, const float* __restrict__ T,
    const float* __restrict__ gt,
    const float* __restrict__ w_ms, const float* __restrict__ w_mt) {
    __shared__ float bx[100];
    __shared__ float wms[256], wmt[256];
    __shared__ float rb[5][8];
    int t = threadIdx.x, bid = blockIdx.x;
    int n = bid >> 6;
    int pix = (bid & 63) * 256 + t;
    if (t < 20) {
        const float* g4 = gt + (size_t)(n * 20 + t) * 4;
        float wmin = floorf(g4[0] * 0.125f);
        float hmin = floorf(g4[1] * 0.125f);
        float wmax = ceilf(g4[2] * 0.125f);
        float hmax = ceilf(g4[3] * 0.125f);
        bx[t]      = wmin;
        bx[20 + t] = wmax;
        bx[40 + t] = hmin;
        bx[60 + t] = hmax;
        bx[80 + t] = 1.f / ((hmax + 1.f - hmin) * (wmax + 1.f - wmin));
    }
    wms[t] = w_ms[t];
    wmt[t] = w_mt[t];
    __syncthreads();
    float h = (float)(pix >> 7), w = (float)(pix & 127);
    float mf = 0.f;
#pragma unroll
    for (int b = 0; b < 20; ++b) {
        bool in = (h >= bx[40 + b]) && (h <= bx[60 + b]) &&
                  (w >= bx[b]) && (w <= bx[20 + b]);
        mf = fmaxf(mf, in ? bx[80 + b] : 0.f);
    }
    float bgi = (mf > 0.f) ? 0.f : 1.f;

    const float* Sp = S + (size_t)n * CHW + pix;
    const float* Tp = T + (size_t)n * CHW + pix;
    float fS = 0, fT = 0, cS = 0, cT = 0;
#pragma unroll 8
    for (int c = 0; c < 256; ++c) {
        float sv = __ldg(Sp + (size_t)c * HW);
        float tv = __ldg(Tp + (size_t)c * HW);
        fS += fabsf(sv); fT += fabsf(tv);
        cS += sv * wms[c]; cT += tv * wmt[c];
    }
    float eS  = __expf(fS * (1.f / 128.f));   // fea/TEMP = sum/128
    float eT  = __expf(fT * (1.f / 128.f));
    float ecS = __expf(cS);                   // bias drops (softmax shift-inv)
    float ecT = __expf(cT);
    int gp = n * HW + pix;
    g_eS[gp] = eS;
    g_eT[gp] = eT;
    g_wpx[gp] = make_float4(eT * mf, eT * bgi, ecS, ecT);

    float v0 = warpSum(eS), v1 = warpSum(eT), v2 = warpSum(ecS);
    float v3 = warpSum(ecT), v4 = warpSum(bgi);
    int lane = t & 31, wid = t >> 5;
    if (lane == 0) {
        rb[0][wid] = v0; rb[1][wid] = v1; rb[2][wid] = v2;
        rb[3][wid] = v3; rb[4][wid] = v4;
    }
    __syncthreads();
    if (t == 0) {
        float z0 = 0, z1 = 0, z2 = 0, z3 = 0, zb = 0;
#pragma unroll
        for (int k = 0; k < 8; ++k) {
            z0 += rb[0][k]; z1 += rb[1][k]; z2 += rb[2][k];
            z3 += rb[3][k]; zb += rb[4][k];
        }
        g_zpart[bid] = make_float4(z0, z1, z2, z3);
        g_bgpart[bid] = zb;
    }
}

// ---------------- pass B: per-(n,c) weighted sums ----------------
__device__ __forceinline__ void acc8(float* a, float sv, float tv, float4 wv) {
    float d = sv - tv, d2 = d * d;
    a[0] += fabsf(sv); a[1] += fabsf(tv);
    a[2] += d2;        a[3] += d;
    a[4] += d2 * wv.x; a[5] += d2 * wv.y;
    a[6] += sv * wv.z; a[7] += tv * wv.w;
}

__global__ __launch_bounds__(256) void passB_kernel(
    const float* __restrict__ S, const float* __restrict__ T) {
    int t = threadIdx.x, bid = blockIdx.x;
    int lane = t & 31, wid = t >> 5;
    int n = bid >> 5;
    int i5 = bid & 31;
    int half = i5 & 1;
    int c0 = ((i5 >> 1) * 8 + wid) * 2;
    size_t base = (size_t)n * CHW + (size_t)c0 * HW + half * 8192;
    const float4* S0 = reinterpret_cast<const float4*>(S + base);
    const float4* S1 = reinterpret_cast<const float4*>(S + base + HW);
    const float4* T0 = reinterpret_cast<const float4*>(T + base);
    const float4* T1 = reinterpret_cast<const float4*>(T + base + HW);
    const float4* W  = g_wpx + (size_t)n * HW + half * 8192;

    float a0[8], a1[8];
#pragma unroll
    for (int i = 0; i < 8; ++i) { a0[i] = 0.f; a1[i] = 0.f; }

#pragma unroll 2
    for (int it = 0; it < 64; ++it) {
        int q4 = it * 32 + lane;
        float4 s0 = __ldg(S0 + q4);
        float4 t0 = __ldg(T0 + q4);
        float4 s1 = __ldg(S1 + q4);
        float4 t1 = __ldg(T1 + q4);
        float4 w0 = __ldg(W + q4 * 4 + 0);
        float4 w1 = __ldg(W + q4 * 4 + 1);
        float4 w2 = __ldg(W + q4 * 4 + 2);
        float4 w3 = __ldg(W + q4 * 4 + 3);
        acc8(a0, s0.x, t0.x, w0); acc8(a0, s0.y, t0.y, w1);
        acc8(a0, s0.z, t0.z, w2); acc8(a0, s0.w, t0.w, w3);
        acc8(a1, s1.x, t1.x, w0); acc8(a1, s1.y, t1.y, w1);
        acc8(a1, s1.z, t1.z, w2); acc8(a1, s1.w, t1.w, w3);
    }
#pragma unroll
    for (int i = 0; i < 8; ++i) { a0[i] = warpSum(a0[i]); a1[i] = warpSum(a1[i]); }
    if (lane == 0) {
        float* dst = g_accP + half * 16384 + n * 256;
#pragma unroll
        for (int q = 0; q < 8; ++q) {
            dst[q * 2048 + c0]     = a0[q];
            dst[q * 2048 + c0 + 1] = a1[q];
        }
    }
}

// ---------------- spatial attention L1: one block per image ----------------
__global__ __launch_bounds__(256) void spat_kernel() {
    int n = blockIdx.x, t = threadIdx.x;
    int lane = t & 31, wid = t >> 5;
    __shared__ float zz[2];
    __shared__ float r2[8];
    if (t < 32) {
        float4 za = g_zpart[n * 64 + t];
        float4 zb = g_zpart[n * 64 + 32 + t];
        float zs = warpSum(za.x + zb.x);
        float zt = warpSum(za.y + zb.y);
        if (t == 0) { zz[0] = zs; zz[1] = zt; }
    }
    __syncthreads();
    float is = 16384.f / zz[0], it = 16384.f / zz[1];
    const float* eSp = g_eS + (size_t)n * HW;
    const float* eTp = g_eT + (size_t)n * HW;
    float v = 0.f;
#pragma unroll 4
    for (int chunk = 0; chunk < 64; ++chunk) {
        int px = chunk * 256 + t;
        v += fabsf(eSp[px] * is - eTp[px] * it);
    }
    v = warpSum(v);
    if (lane == 0) r2[wid] = v;
    __syncthreads();
    if (t == 0) {
        float s2 = 0;
#pragma unroll
        for (int k = 0; k < 8; ++k) s2 += r2[k];
        g_spart[n] = s2;
    }
}

// ---------------- epilogue: channel softmax, MLPs, combine ----------------
#define ACC(q, i) (g_accP[(q) * 2048 + (i)] + g_accP[16384 + (q) * 2048 + (i)])

// Coalesced MLP: warp wid computes output rows j = wid + 8*jj.
// Lane covers a contiguous chunk of the row -> warp LDGs are contiguous.
// ctx: smem[2048] (8 images x 256). outp may alias ctx (phase-separated).
__device__ void channel_mlp(const float* __restrict__ ctx,
                            const float* __restrict__ w1, const float* __restrict__ b1,
                            const float* __restrict__ gam, const float* __restrict__ bet,
                            const float* __restrict__ w2, const float* __restrict__ b2,
                            float* __restrict__ yS,          // smem [1024]
                            float* __restrict__ outp) {      // smem [2048]
    int t = threadIdx.x, wid = t >> 5, lane = t & 31;
    const float4* ctx4 = reinterpret_cast<const float4*>(ctx);
    // ---- L1: y[n][j] = b1[j] + ctx[n] . w1[j] ----
#pragma unroll 2
    for (int jj = 0; jj < 16; ++jj) {
        int j = wid + 8 * jj;
        const float4* wrow = reinterpret_cast<const float4*>(w1 + (size_t)j * 256);
        float4 wv0 = __ldg(wrow + lane * 2);
        float4 wv1 = __ldg(wrow + lane * 2 + 1);
        float p[8];
#pragma unroll
        for (int n = 0; n < 8; ++n) {
            float4 c0 = ctx4[n * 64 + lane * 2];
            float4 c1 = ctx4[n * 64 + lane * 2 + 1];
            p[n] = wv0.x * c0.x + wv0.y * c0.y + wv0.z * c0.z + wv0.w * c0.w
                 + wv1.x * c1.x + wv1.y * c1.y + wv1.z * c1.z + wv1.w * c1.w;
        }
#pragma unroll
        for (int n = 0; n < 8; ++n) p[n] = warpSum(p[n]);
        float bj = __ldg(b1 + j);
#pragma unroll
        for (int n = 0; n < 8; ++n)
            if (lane == n) yS[n * 128 + j] = p[n] + bj;
    }
    __syncthreads();
    // ---- LayerNorm + ReLU: warp wid <-> image wid ----
    {
        float yv[4];
#pragma unroll
        for (int k = 0; k < 4; ++k) yv[k] = yS[wid * 128 + lane + 32 * k];
        float s = 0, s2 = 0;
#pragma unroll
        for (int k = 0; k < 4; ++k) { s += yv[k]; s2 += yv[k] * yv[k]; }
        s = warpSum(s); s2 = warpSum(s2);
        float mean = s * (1.f / 128.f);
        float var = s2 * (1.f / 128.f) - mean * mean;
        float inv = rsqrtf(var + 1e-5f);
#pragma unroll
        for (int k = 0; k < 4; ++k) {
            int j = lane + 32 * k;
            float y = (yv[k] - mean) * inv * __ldg(gam + j) + __ldg(bet + j);
            yS[wid * 128 + j] = fmaxf(y, 0.f);
        }
    }
    __syncthreads();
    // ---- L2: out[n][c] = b2[c] + act[n] . w2[c] ----
    const float4* yS4 = reinterpret_cast<const float4*>(yS);
#pragma unroll 2
    for (int cc = 0; cc < 32; ++cc) {
        int c = wid + 8 * cc;
        float4 wv = __ldg(reinterpret_cast<const float4*>(w2 + (size_t)c * 128) + lane);
        float p[8];
#pragma unroll
        for (int n = 0; n < 8; ++n) {
            float4 a = yS4[n * 32 + lane];
            p[n] = wv.x * a.x + wv.y * a.y + wv.z * a.z + wv.w * a.w;
        }
#pragma unroll
        for (int n = 0; n < 8; ++n) p[n] = warpSum(p[n]);
        float bc = __ldg(b2 + c);
#pragma unroll
        for (int n = 0; n < 8; ++n)
            if (lane == n) outp[n * 256 + c] = p[n] + bc;
    }
    __syncthreads();
}

__global__ __launch_bounds__(256) void final_kernel(
    const float* __restrict__ w1_s, const float* __restrict__ b1_s,
    const float* __restrict__ g_s,  const float* __restrict__ be_s,
    const float* __restrict__ w2_s, const float* __restrict__ b2_s,
    const float* __restrict__ w1_t, const float* __restrict__ b1_t,
    const float* __restrict__ g_t,  const float* __restrict__ be_t,
    const float* __restrict__ w2_t, const float* __restrict__ b2_t,
    float* __restrict__ out) {
    __shared__ __align__(16) float shFS[2048];
    __shared__ __align__(16) float shFT[2048];
    __shared__ __align__(16) float shCS[2048];
    __shared__ __align__(16) float shCT[2048];
    __shared__ __align__(16) float shY[1024];
    __shared__ float shZT[8], shZcS[8], shZcT[8], shBG[8];
    __shared__ float shZ[16];
    __shared__ float shR[8];
    int t = threadIdx.x, w = t >> 5, lane = t & 31;
    {
        float4 za = g_zpart[w * 64 + lane];
        float4 zb = g_zpart[w * 64 + 32 + lane];
        float zt  = warpSum(za.y + zb.y);
        float zcs = warpSum(za.z + zb.z);
        float zct = warpSum(za.w + zb.w);
        float bg  = warpSum(g_bgpart[w * 64 + lane] + g_bgpart[w * 64 + 32 + lane]);
        if (lane == 0) { shZT[w] = zt; shZcS[w] = zcs; shZcT[w] = zct; shBG[w] = bg; }
    }
    __syncthreads();
#pragma unroll
    for (int n = 0; n < 8; ++n) {
        int i = n * 256 + t;
        shFS[i] = __expf(ACC(0, i) * (1.f / 8192.f));   // ch/TEMP = sum/8192
        shFT[i] = __expf(ACC(1, i) * (1.f / 8192.f));
        shCS[i] = ACC(6, i) / shZcS[n];
        shCT[i] = ACC(7, i) / shZcT[n];
    }
    __syncthreads();
    {
        float zS = 0, zT = 0;
#pragma unroll
        for (int k = 0; k < 8; ++k) {
            int c = lane + 32 * k;
            zS += shFS[w * 256 + c];
            zT += shFT[w * 256 + c];
        }
        zS = warpSum(zS); zT = warpSum(zT);
        if (lane == 0) { shZ[w] = zS; shZ[8 + w] = zT; }
    }
    __syncthreads();
    channel_mlp(shCS, w1_s, b1_s, g_s, be_s, w2_s, b2_s, shY, shCS);  // -> add_s
    channel_mlp(shCT, w1_t, b1_t, g_t, be_t, w2_t, b2_t, shY, shCT);  // -> add_t

    float acc = 0.f;
#pragma unroll
    for (int n = 0; n < 8; ++n) {
        int i = n * 256 + t;
        float cS = 256.f * shFS[i] / shZ[n];
        float cT = 256.f * shFT[i] / shZ[8 + n];
        float wn = cT * (16384.f / shZT[n]);
        float bgc = shBG[n];
        float bgw = (bgc > 0.f) ? (1.f / bgc) : 0.f;
        float fg = wn * ACC(4, i);
        float bg = wn * bgw * ACC(5, i);
        float mC = fabsf(cS - cT);
        float delta = shCS[i] - shCT[i];
        float rel = ACC(2, i) + 2.f * delta * ACC(3, i)
                    + 16384.f * delta * delta;
        acc += 1e-3f * fg + 5e-4f * bg + 1e-3f * mC + 5e-6f * rel;
    }
    acc = warpSum(acc);
    if (lane == 0) shR[w] = acc;
    __syncthreads();
    if (t < 32) {
        float x = (t < 8) ? shR[t] : 0.f;
        x = warpSum(x);
        if (t == 0) {
            float sp = 0;
#pragma unroll
            for (int k = 0; k < 8; ++k) sp += g_spart[k];
            out[0] = (x + 1e-3f * sp) * 0.125f;
        }
    }
}

extern "C" void kernel_launch(void* const* d_in, const int* in_sizes, int n_in,
                              void* d_out, int out_size) {
    const float* S    = (const float*)d_in[0];
    const float* T    = (const float*)d_in[1];
    const float* gt   = (const float*)d_in[2];
    const float* w_ms = (const float*)d_in[3];
    const float* w_mt = (const float*)d_in[5];
    const float* w1_s = (const float*)d_in[7];
    const float* b1_s = (const float*)d_in[8];
    const float* g_s  = (const float*)d_in[9];
    const float* be_s = (const float*)d_in[10];
    const float* w2_s = (const float*)d_in[11];
    const float* b2_s = (const float*)d_in[12];
    const float* w1_t = (const float*)d_in[13];
    const float* b1_t = (const float*)d_in[14];
    const float* g_t  = (const float*)d_in[15];
    const float* be_t = (const float*)d_in[16];
    const float* w2_t = (const float*)d_in[17];
    const float* b2_t = (const float*)d_in[18];

    passA_kernel<<<512, 256>>>(S, T, gt, w_ms, w_mt);
    passB_kernel<<<256, 256>>>(S, T);
    spat_kernel<<<8, 256>>>();
    final_kernel<<<1, 256>>>(w1_s, b1_s, g_s, be_s, w2_s, b2_s,
                             w1_t, b1_t, g_t, be_t, w2_t, b2_t,
                             (float*)d_out);
}

// round 14
// speedup vs baseline: 2.6629x; 1.6889x over previous
#include <cuda_runtime.h>

#define HW    16384
#define CCH   256
#define CHW   4194304   // 256*16384
#define NIMG  8

// per-(n,c) partial sums, two pixel-halves:
// g_accP[h*16384 + q*2048 + n*256 + c]
// q: 0 chS, 1 chT, 2 SS2, 3 SD, 4 FG, 5 BG, 6 CXS, 7 CXT
__device__ float  g_accP[2 * 16384];
__device__ float4 g_wpx[NIMG * HW];   // per-pixel: eT*mf, eT*bgi, ecS, ecT
__device__ float  g_eS[NIMG * HW];
__device__ float  g_eT[NIMG * HW];
__device__ float4 g_zpart[512];       // per passA block: zfeaS, zfeaT, zcmS, zcmT
__device__ float  g_bgpart[512];      // per passA block: bg pixel count
__device__ float  g_spart[NIMG];      // per-image spatial L1
__device__ float  g_ctx[2 * 2048];    // [side][n][c] spatial-pool context
__device__ float  g_y[2 * 1024];      // [side][n][j] pre-LN hidden
__device__ float  g_add[2 * 2048];    // [side][n][c] channel_add output

__device__ __forceinline__ float warpSum(float v) {
#pragma unroll
    for (int o = 16; o; o >>= 1) v += __shfl_xor_sync(0xffffffffu, v, o);
    return v;
}

// ---------------- pass A: mask + per-pixel channel sums ----------------
// grid 512 = 8 images x 64 blocks of 256 pixels; thread t <-> pixel.
__global__ __launch_bounds__(256) void passA_kernel(
    const float* __restrict__ S, const float* __restrict__ T,
    const float* __restrict__ gt,
    const float* __restrict__ w_ms, const float* __restrict__ w_mt) {
    __shared__ float bx[100];
    __shared__ float wms[256], wmt[256];
    __shared__ float rb[5][8];
    int t = threadIdx.x, bid = blockIdx.x;
    int n = bid >> 6;
    int pix = (bid & 63) * 256 + t;
    if (t < 20) {
        const float* g4 = gt + (size_t)(n * 20 + t) * 4;
        float wmin = floorf(g4[0] * 0.125f);
        float hmin = floorf(g4[1] * 0.125f);
        float wmax = ceilf(g4[2] * 0.125f);
        float hmax = ceilf(g4[3] * 0.125f);
        bx[t]      = wmin;
        bx[20 + t] = wmax;
        bx[40 + t] = hmin;
        bx[60 + t] = hmax;
        bx[80 + t] = 1.f / ((hmax + 1.f - hmin) * (wmax + 1.f - wmin));
    }
    wms[t] = w_ms[t];
    wmt[t] = w_mt[t];
    __syncthreads();
    float h = (float)(pix >> 7), w = (float)(pix & 127);
    float mf = 0.f;
#pragma unroll
    for (int b = 0; b < 20; ++b) {
        bool in = (h >= bx[40 + b]) && (h <= bx[60 + b]) &&
                  (w >= bx[b]) && (w <= bx[20 + b]);
        mf = fmaxf(mf, in ? bx[80 + b] : 0.f);
    }
    float bgi = (mf > 0.f) ? 0.f : 1.f;

    const float* Sp = S + (size_t)n * CHW + pix;
    const float* Tp = T + (size_t)n * CHW + pix;
    float fS = 0, fT = 0, cS = 0, cT = 0;
#pragma unroll 8
    for (int c = 0; c < 256; ++c) {
        float sv = __ldg(Sp + (size_t)c * HW);
        float tv = __ldg(Tp + (size_t)c * HW);
        fS += fabsf(sv); fT += fabsf(tv);
        cS += sv * wms[c]; cT += tv * wmt[c];
    }
    float eS  = __expf(fS * (1.f / 128.f));   // fea/TEMP = sum/128
    float eT  = __expf(fT * (1.f / 128.f));
    float ecS = __expf(cS);                   // bias drops (softmax shift-inv)
    float ecT = __expf(cT);
    int gp = n * HW + pix;
    g_eS[gp] = eS;
    g_eT[gp] = eT;
    g_wpx[gp] = make_float4(eT * mf, eT * bgi, ecS, ecT);

    float v0 = warpSum(eS), v1 = warpSum(eT), v2 = warpSum(ecS);
    float v3 = warpSum(ecT), v4 = warpSum(bgi);
    int lane = t & 31, wid = t >> 5;
    if (lane == 0) {
        rb[0][wid] = v0; rb[1][wid] = v1; rb[2][wid] = v2;
        rb[3][wid] = v3; rb[4][wid] = v4;
    }
    __syncthreads();
    if (t == 0) {
        float z0 = 0, z1 = 0, z2 = 0, z3 = 0, zb = 0;
#pragma unroll
        for (int k = 0; k < 8; ++k) {
            z0 += rb[0][k]; z1 += rb[1][k]; z2 += rb[2][k];
            z3 += rb[3][k]; zb += rb[4][k];
        }
        g_zpart[bid] = make_float4(z0, z1, z2, z3);
        g_bgpart[bid] = zb;
    }
}

// ---------------- pass B: per-(n,c) weighted sums ----------------
__device__ __forceinline__ void acc8(float* a, float sv, float tv, float4 wv) {
    float d = sv - tv, d2 = d * d;
    a[0] += fabsf(sv); a[1] += fabsf(tv);
    a[2] += d2;        a[3] += d;
    a[4] += d2 * wv.x; a[5] += d2 * wv.y;
    a[6] += sv * wv.z; a[7] += tv * wv.w;
}

__global__ __launch_bounds__(256) void passB_kernel(
    const float* __restrict__ S, const float* __restrict__ T) {
    int t = threadIdx.x, bid = blockIdx.x;
    int lane = t & 31, wid = t >> 5;
    int n = bid >> 5;
    int i5 = bid & 31;
    int half = i5 & 1;
    int c0 = ((i5 >> 1) * 8 + wid) * 2;
    size_t base = (size_t)n * CHW + (size_t)c0 * HW + half * 8192;
    const float4* S0 = reinterpret_cast<const float4*>(S + base);
    const float4* S1 = reinterpret_cast<const float4*>(S + base + HW);
    const float4* T0 = reinterpret_cast<const float4*>(T + base);
    const float4* T1 = reinterpret_cast<const float4*>(T + base + HW);
    const float4* W  = g_wpx + (size_t)n * HW + half * 8192;

    float a0[8], a1[8];
#pragma unroll
    for (int i = 0; i < 8; ++i) { a0[i] = 0.f; a1[i] = 0.f; }

#pragma unroll 2
    for (int it = 0; it < 64; ++it) {
        int q4 = it * 32 + lane;
        float4 s0 = __ldg(S0 + q4);
        float4 t0 = __ldg(T0 + q4);
        float4 s1 = __ldg(S1 + q4);
        float4 t1 = __ldg(T1 + q4);
        float4 w0 = __ldg(W + q4 * 4 + 0);
        float4 w1 = __ldg(W + q4 * 4 + 1);
        float4 w2 = __ldg(W + q4 * 4 + 2);
        float4 w3 = __ldg(W + q4 * 4 + 3);
        acc8(a0, s0.x, t0.x, w0); acc8(a0, s0.y, t0.y, w1);
        acc8(a0, s0.z, t0.z, w2); acc8(a0, s0.w, t0.w, w3);
        acc8(a1, s1.x, t1.x, w0); acc8(a1, s1.y, t1.y, w1);
        acc8(a1, s1.z, t1.z, w2); acc8(a1, s1.w, t1.w, w3);
    }
#pragma unroll
    for (int i = 0; i < 8; ++i) { a0[i] = warpSum(a0[i]); a1[i] = warpSum(a1[i]); }
    if (lane == 0) {
        float* dst = g_accP + half * 16384 + n * 256;
#pragma unroll
        for (int q = 0; q < 8; ++q) {
            dst[q * 2048 + c0]     = a0[q];
            dst[q * 2048 + c0 + 1] = a1[q];
        }
    }
}

// ---------------- spat (blocks 0-7) + ctx prep (blocks 8-15) ----------------
#define ACC(q, i) (g_accP[(q) * 2048 + (i)] + g_accP[16384 + (q) * 2048 + (i)])

__global__ __launch_bounds__(256) void spatprep_kernel() {
    int bid = blockIdx.x, t = threadIdx.x;
    int lane = t & 31, wid = t >> 5;
    if (bid < 8) {           // spatial attention L1 for image n
        int n = bid;
        __shared__ float zz[2];
        __shared__ float r2[8];
        if (t < 32) {
            float4 za = g_zpart[n * 64 + t];
            float4 zb = g_zpart[n * 64 + 32 + t];
            float zs = warpSum(za.x + zb.x);
            float zt = warpSum(za.y + zb.y);
            if (t == 0) { zz[0] = zs; zz[1] = zt; }
        }
        __syncthreads();
        float is = 16384.f / zz[0], it = 16384.f / zz[1];
        const float* eSp = g_eS + (size_t)n * HW;
        const float* eTp = g_eT + (size_t)n * HW;
        float v = 0.f;
#pragma unroll 4
        for (int chunk = 0; chunk < 64; ++chunk) {
            int px = chunk * 256 + t;
            v += fabsf(eSp[px] * is - eTp[px] * it);
        }
        v = warpSum(v);
        if (lane == 0) r2[wid] = v;
        __syncthreads();
        if (t == 0) {
            float s2 = 0;
#pragma unroll
            for (int k = 0; k < 8; ++k) s2 += r2[k];
            g_spart[n] = s2;
        }
    } else {                 // ctx prep for image n
        int n = bid - 8;
        __shared__ float zz[2];
        if (t < 32) {
            float4 za = g_zpart[n * 64 + t];
            float4 zb = g_zpart[n * 64 + 32 + t];
            float zcs = warpSum(za.z + zb.z);
            float zct = warpSum(za.w + zb.w);
            if (t == 0) { zz[0] = zcs; zz[1] = zct; }
        }
        __syncthreads();
        int i = n * 256 + t;
        g_ctx[i]        = ACC(6, i) / zz[0];
        g_ctx[2048 + i] = ACC(7, i) / zz[1];
    }
}

// ---------------- mlp1: y[s][n][j] = b1[j] + ctx[s][n] . w1[j] ----------------
// 64 blocks x 8 warps = 512 warps; warp W: s=W>>8, n=(W>>5)&7, j0=(W&31)*4.
__global__ __launch_bounds__(256) void mlp1_kernel(
    const float* __restrict__ w1_s, const float* __restrict__ b1_s,
    const float* __restrict__ w1_t, const float* __restrict__ b1_t) {
    int t = threadIdx.x;
    int lane = t & 31, wid = t >> 5;
    int W = blockIdx.x * 8 + wid;
    int s = W >> 8, r = W & 255;
    int n = r >> 5, j0 = (r & 31) * 4;
    const float* w1 = s ? w1_t : w1_s;
    const float* b1 = s ? b1_t : b1_s;
    const float4* ctx4 = reinterpret_cast<const float4*>(g_ctx + s * 2048 + n * 256);
    float4 c0 = ctx4[lane * 2];
    float4 c1 = ctx4[lane * 2 + 1];
    float p[4];
#pragma unroll
    for (int jj = 0; jj < 4; ++jj) {
        const float4* wr = reinterpret_cast<const float4*>(w1 + (size_t)(j0 + jj) * 256);
        float4 wv0 = __ldg(wr + lane * 2);
        float4 wv1 = __ldg(wr + lane * 2 + 1);
        p[jj] = wv0.x * c0.x + wv0.y * c0.y + wv0.z * c0.z + wv0.w * c0.w
              + wv1.x * c1.x + wv1.y * c1.y + wv1.z * c1.z + wv1.w * c1.w;
    }
#pragma unroll
    for (int jj = 0; jj < 4; ++jj) p[jj] = warpSum(p[jj]);
    if (lane < 4)
        g_y[s * 1024 + n * 128 + j0 + lane] = p[lane] + __ldg(b1 + j0 + lane);
}

// ---------------- mlp2: LN+ReLU then out[s][n][c] = b2[c] + act . w2[c] -------
// 64 blocks x 8 warps = 512 warps; warp W: s=W>>8, n=(W>>5)&7, c0=(W&31)*8.
__global__ __launch_bounds__(256) void mlp2_kernel(
    const float* __restrict__ g_s,  const float* __restrict__ be_s,
    const float* __restrict__ w2_s, const float* __restrict__ b2_s,
    const float* __restrict__ g_t,  const float* __restrict__ be_t,
    const float* __restrict__ w2_t, const float* __restrict__ b2_t) {
    __shared__ __align__(16) float act[2048];
    int t = threadIdx.x;
    int lane = t & 31, wid = t >> 5;
    // LN: 16 rows (side,n); warp handles rows wid and wid+8
#pragma unroll
    for (int h = 0; h < 2; ++h) {
        int R = wid + 8 * h;                 // R = s*8 + n
        int sS = R >> 3;
        const float4* y4 = reinterpret_cast<const float4*>(g_y + R * 128);
        float4 yv = __ldg(y4 + lane);
        float sm = yv.x + yv.y + yv.z + yv.w;
        float sq = yv.x * yv.x + yv.y * yv.y + yv.z * yv.z + yv.w * yv.w;
        sm = warpSum(sm); sq = warpSum(sq);
        float mean = sm * (1.f / 128.f);
        float var = sq * (1.f / 128.f) - mean * mean;
        float inv = rsqrtf(var + 1e-5f);
        const float4* gam4 = reinterpret_cast<const float4*>(sS ? g_t : g_s);
        const float4* bet4 = reinterpret_cast<const float4*>(sS ? be_t : be_s);
        float4 gv = __ldg(gam4 + lane);
        float4 bv = __ldg(bet4 + lane);
        float4 av;
        av.x = fmaxf((yv.x - mean) * inv * gv.x + bv.x, 0.f);
        av.y = fmaxf((yv.y - mean) * inv * gv.y + bv.y, 0.f);
        av.z = fmaxf((yv.z - mean) * inv * gv.z + bv.z, 0.f);
        av.w = fmaxf((yv.w - mean) * inv * gv.w + bv.w, 0.f);
        reinterpret_cast<float4*>(act)[R * 32 + lane] = av;
    }
    __syncthreads();
    int W = blockIdx.x * 8 + wid;
    int s = W >> 8, r = W & 255;
    int n = r >> 5, c0 = (r & 31) * 8;
    const float* w2 = s ? w2_t : w2_s;
    const float* b2 = s ? b2_t : b2_s;
    float4 a = reinterpret_cast<const float4*>(act)[(s * 8 + n) * 32 + lane];
    float p[8];
#pragma unroll
    for (int cc = 0; cc < 8; ++cc) {
        float4 wv = __ldg(reinterpret_cast<const float4*>(w2 + (size_t)(c0 + cc) * 128) + lane);
        p[cc] = wv.x * a.x + wv.y * a.y + wv.z * a.z + wv.w * a.w;
    }
#pragma unroll
    for (int cc = 0; cc < 8; ++cc) p[cc] = warpSum(p[cc]);
    if (lane < 8)
        g_add[s * 2048 + n * 256 + c0 + lane] = p[lane] + __ldg(b2 + c0 + lane);
}

// ---------------- combine ----------------
__global__ __launch_bounds__(256) void combine_kernel(float* __restrict__ out) {
    __shared__ __align__(16) float shFS[2048];
    __shared__ __align__(16) float shFT[2048];
    __shared__ float shZT[8], shBG[8];
    __shared__ float shZ[16];
    __shared__ float shR[8];
    int t = threadIdx.x, w = t >> 5, lane = t & 31;
    {
        float4 za = g_zpart[w * 64 + lane];
        float4 zb = g_zpart[w * 64 + 32 + lane];
        float zt  = warpSum(za.y + zb.y);
        float bg  = warpSum(g_bgpart[w * 64 + lane] + g_bgpart[w * 64 + 32 + lane]);
        if (lane == 0) { shZT[w] = zt; shBG[w] = bg; }
    }
    __syncthreads();
#pragma unroll
    for (int n = 0; n < 8; ++n) {
        int i = n * 256 + t;
        shFS[i] = __expf(ACC(0, i) * (1.f / 8192.f));   // ch/TEMP = sum/8192
        shFT[i] = __expf(ACC(1, i) * (1.f / 8192.f));
    }
    __syncthreads();
    {
        float zS = 0, zT = 0;
#pragma unroll
        for (int k = 0; k < 8; ++k) {
            int c = lane + 32 * k;
            zS += shFS[w * 256 + c];
            zT += shFT[w * 256 + c];
        }
        zS = warpSum(zS); zT = warpSum(zT);
        if (lane == 0) { shZ[w] = zS; shZ[8 + w] = zT; }
    }
    __syncthreads();
    float acc = 0.f;
#pragma unroll
    for (int n = 0; n < 8; ++n) {
        int i = n * 256 + t;
        float cS = 256.f * shFS[i] / shZ[n];
        float cT = 256.f * shFT[i] / shZ[8 + n];
        float wn = cT * (16384.f / shZT[n]);
        float bgc = shBG[n];
        float bgw = (bgc > 0.f) ? (1.f / bgc) : 0.f;
        float fg = wn * ACC(4, i);
        float bg = wn * bgw * ACC(5, i);
        float mC = fabsf(cS - cT);
        float delta = g_add[i] - g_add[2048 + i];
        float rel = ACC(2, i) + 2.f * delta * ACC(3, i)
                    + 16384.f * delta * delta;
        acc += 1e-3f * fg + 5e-4f * bg + 1e-3f * mC + 5e-6f * rel;
    }
    acc = warpSum(acc);
    if (lane == 0) shR[w] = acc;
    __syncthreads();
    if (t < 32) {
        float x = (t < 8) ? shR[t] : 0.f;
        x = warpSum(x);
        if (t == 0) {
            float sp = 0;
#pragma unroll
            for (int k = 0; k < 8; ++k) sp += g_spart[k];
            out[0] = (x + 1e-3f * sp) * 0.125f;
        }
    }
}

extern "C" void kernel_launch(void* const* d_in, const int* in_sizes, int n_in,
                              void* d_out, int out_size) {
    const float* S    = (const float*)d_in[0];
    const float* T    = (const float*)d_in[1];
    const float* gt   = (const float*)d_in[2];
    const float* w_ms = (const float*)d_in[3];
    const float* w_mt = (const float*)d_in[5];
    const float* w1_s = (const float*)d_in[7];
    const float* b1_s = (const float*)d_in[8];
    const float* g_s  = (const float*)d_in[9];
    const float* be_s = (const float*)d_in[10];
    const float* w2_s = (const float*)d_in[11];
    const float* b2_s = (const float*)d_in[12];
    const float* w1_t = (const float*)d_in[13];
    const float* b1_t = (const float*)d_in[14];
    const float* g_t  = (const float*)d_in[15];
    const float* be_t = (const float*)d_in[16];
    const float* w2_t = (const float*)d_in[17];
    const float* b2_t = (const float*)d_in[18];

    passA_kernel<<<512, 256>>>(S, T, gt, w_ms, w_mt);
    passB_kernel<<<256, 256>>>(S, T);
    spatprep_kernel<<<16, 256>>>();
    mlp1_kernel<<<64, 256>>>(w1_s, b1_s, w1_t, b1_t);
    mlp2_kernel<<<64, 256>>>(g_s, be_s, w2_s, b2_s, g_t, be_t, w2_t, b2_t);
    combine_kernel<<<1, 256>>>((float*)d_out);
}